// round 16
// baseline (speedup 1.0000x reference)
#include <cuda_runtime.h>
#include <cuda_fp16.h>
#include <cstdint>

#define BB 32
#define DD 128
#define LC 2048
#define LQ 512
#define NEG (-1e30f)

__device__ float g_S[(size_t)BB*LC*LQ];
__device__ __half g_E[(size_t)BB*LC*LQ];
__device__ float g_T[(size_t)BB*LQ*DD];
__device__ float g_sub0[BB*LC], g_sub1[BB*LQ];
__device__ float g_rmax[BB*LC], g_rsum[BB*LC];
__device__ float g_Z[BB*LQ];
__device__ float g_Zp[BB*16*LQ];
__device__ float g_Rblk[BB*16];
__device__ float g_f[BB*LC];
__device__ __half g_QTh[(size_t)BB*LQ*DD];

__device__ __forceinline__ uint32_t smem_u32(const void* p) {
    uint32_t a;
    asm("{ .reg .u64 t; cvta.to.shared.u64 t, %1; cvt.u32.u64 %0, t; }" : "=r"(a) : "l"(p));
    return a;
}
__device__ __forceinline__ void split2h(float x, __half& h, __half& l) {
    h = __float2half_rn(x);
    l = __float2half_rn(x - __half2float(h));
}
__device__ __forceinline__ void ldsm4(uint32_t* r, uint32_t a) {
    asm volatile("ldmatrix.sync.aligned.m8n8.x4.shared.b16 {%0,%1,%2,%3}, [%4];"
        : "=r"(r[0]), "=r"(r[1]), "=r"(r[2]), "=r"(r[3]) : "r"(a));
}
__device__ __forceinline__ void ldsm4t(uint32_t* r, uint32_t a) {
    asm volatile("ldmatrix.sync.aligned.m8n8.x4.trans.shared.b16 {%0,%1,%2,%3}, [%4];"
        : "=r"(r[0]), "=r"(r[1]), "=r"(r[2]), "=r"(r[3]) : "r"(a));
}
__device__ __forceinline__ void mma_f16(float* c, const uint32_t* a, const uint32_t* b) {
    asm volatile("mma.sync.aligned.m16n8k16.row.col.f32.f16.f16.f32 "
        "{%0,%1,%2,%3}, {%4,%5,%6,%7}, {%8,%9}, {%0,%1,%2,%3};"
        : "+f"(c[0]), "+f"(c[1]), "+f"(c[2]), "+f"(c[3])
        : "r"(a[0]), "r"(a[1]), "r"(a[2]), "r"(a[3]), "r"(b[0]), "r"(b[1]));
}
template<int SB, int NF, int LOFF>
__device__ __forceinline__ void chunk_A2B2(float acc[2][NF][4], uint32_t uA, uint32_t uB) {
#pragma unroll
    for (int ks = 0; ks < 2; ks++) {
        uint32_t aH[2][4], aL[2][4], bH[NF * 2], bL[NF * 2];
#pragma unroll
        for (int mf = 0; mf < 2; mf++) {
            ldsm4(aH[mf], uA + mf * 1280 + ks * 32);
            ldsm4(aL[mf], uA + 10240 + mf * 1280 + ks * 32);
        }
#pragma unroll
        for (int nb = 0; nb < NF / 2; nb++) {
            ldsm4t(&bH[nb * 4], uB + ks * 16 * SB + nb * 32);
            ldsm4t(&bL[nb * 4], uB + LOFF + ks * 16 * SB + nb * 32);
        }
#pragma unroll
        for (int mf = 0; mf < 2; mf++)
#pragma unroll
            for (int nf = 0; nf < NF; nf++) {
                mma_f16(acc[mf][nf], aH[mf], &bH[nf * 2]);
                mma_f16(acc[mf][nf], aH[mf], &bL[nf * 2]);
                mma_f16(acc[mf][nf], aL[mf], &bH[nf * 2]);
            }
    }
}
template<int SB, int NF>
__device__ __forceinline__ void chunk_A1B1(float acc[2][NF][4], uint32_t uA, uint32_t uB) {
#pragma unroll
    for (int ks = 0; ks < 2; ks++) {
        uint32_t aH[2][4], bH[NF * 2];
#pragma unroll
        for (int mf = 0; mf < 2; mf++)
            ldsm4(aH[mf], uA + mf * 1280 + ks * 32);
#pragma unroll
        for (int nb = 0; nb < NF / 2; nb++)
            ldsm4t(&bH[nb * 4], uB + ks * 16 * SB + nb * 32);
#pragma unroll
        for (int mf = 0; mf < 2; mf++)
#pragma unroll
            for (int nf = 0; nf < NF; nf++)
                mma_f16(acc[mf][nf], aH[mf], &bH[nf * 2]);
    }
}
__device__ __forceinline__ void loadA32s(char* sm, const __half* __restrict__ gh,
                                         size_t gs, int tid) {
    int r = tid >> 1, c16 = (tid & 1) * 16;
    const char* sh = (const char*)(gh + (size_t)r * gs + c16);
    char* d = sm + r * 80 + c16 * 2;
    *(uint4*)d = *(const uint4*)sh;  *(uint4*)(d + 16) = *(const uint4*)(sh + 16);
}
__device__ __forceinline__ void loadB128s(char* smB, const __half* __restrict__ gh,
                                          size_t gs, int tid) {
    int r = tid >> 3, c16 = (tid & 7) * 16;
    const char* sh = (const char*)(gh + (size_t)r * gs + c16);
    char* d = smB + r * 272 + c16 * 2;
    *(uint4*)d = *(const uint4*)sh;  *(uint4*)(d + 16) = *(const uint4*)(sh + 16);
}

// ---------------- prep ----------------
__global__ void k_zero() {
    int i = blockIdx.x * 256 + threadIdx.x;
    if (i < BB * LQ) g_sub1[i] = 0.f;
}
__global__ void k_sub0(const float* __restrict__ C, const float* __restrict__ w) {
    int b = blockIdx.y, c = blockIdx.x * 256 + threadIdx.x;
    const float* Cb = C + (size_t)b * DD * LC;
    float acc = 0.f;
#pragma unroll 8
    for (int d = 0; d < DD; d++) acc += Cb[(size_t)d * LC + c] * w[d];
    g_sub0[b * LC + c] = acc;
}
__global__ void k_tsplit(const float* __restrict__ src, const float* __restrict__ wsub) {
    __shared__ float t[32][33];
    __shared__ float ps[32];
    int b = blockIdx.z, x0 = blockIdx.x * 32, d0 = blockIdx.y * 32;
    int tx = threadIdx.x, ty = threadIdx.y;
    if (ty == 0) ps[tx] = 0.f;
    __syncthreads();
    const float* s = src + ((size_t)b * DD + d0) * LQ + x0;
    float psum = 0.f;
#pragma unroll
    for (int i = 0; i < 4; i++) {
        int d = ty + i * 8;
        float v = s[(size_t)d * LQ + tx];
        psum += v * wsub[d0 + d];
        t[d][tx] = v;
    }
    atomicAdd(&ps[tx], psum);
    __syncthreads();
#pragma unroll
    for (int i = 0; i < 4; i++) {
        int x = ty + i * 8;
        size_t o = ((size_t)b * LQ + x0 + x) * DD + d0 + tx;
        g_QTh[o] = __float2half_rn(t[tx][x]);
    }
    if (ty == 0) atomicAdd(g_sub1 + b * LQ + x0 + tx, ps[tx]);
}

// ---------------- GEMM S: coalesced staging transpose for A tiles ----------------
#define SBUF 37888
#define S_WML 75776
#define S_STG 76800
#define SMEM_S (S_STG + 32 * 132 * 4)
__global__ __launch_bounds__(256) void k_S(const float* __restrict__ C,
                                           const float* __restrict__ Q,
                                           const float* __restrict__ w4mlu,
                                           const float* __restrict__ bias) {
    extern __shared__ char sm[];
    float* wml = (float*)(sm + S_WML);
    float* stg = (float*)(sm + S_STG);
    int tid = threadIdx.x, lane = tid & 31, w = tid >> 5, wm = w & 3, wn = w >> 2;
    int b = blockIdx.z, m0 = blockIdx.y * 128, n0 = blockIdx.x * 128;
    if (tid < 128) wml[tid] = w4mlu[tid];
    __syncthreads();
    const float* Cb = C + (size_t)b * DD * LC + m0;
    const float* Qb = Q + (size_t)b * DD * LQ + n0;
    uint32_t su = smem_u32(sm);
    uint32_t uA = su + (wm * 32 + (lane & 15)) * 80 + (lane >> 4) * 16;
    uint32_t uB = su + 20480 + (lane & 15) * 272 + (wn * 64 + (lane >> 4) * 8) * 2;
    int ra = tid >> 1, ds = (tid & 1) * 16;
    int rb = tid >> 3, cq = (tid & 7) * 16;
    float acc[2][8][4] = {};
    // stage: coalesced load of C[k0..k0+31][m0..m0+127] into stg[32][132]
    auto stage = [&](int k0) {
#pragma unroll
        for (int j = 0; j < 4; j++) {
            int idx = j * 256 + tid;          // 1024 float4s
            int row = idx >> 5, c4 = (idx & 31) * 4;
            float4 v = *(const float4*)(Cb + (size_t)(k0 + row) * LC + c4);
            *(float4*)&stg[row * 132 + c4] = v;
        }
    };
    // build MMA tiles for chunk at k0 into buffer koff (A from stg, B from gmem Q)
    auto build = [&](int koff, int k0) {
        __align__(16) __half hh[16], ll[16];
#pragma unroll
        for (int j = 0; j < 16; j++) {
            float v = stg[(ds + j) * 132 + ra] * wml[k0 + ds + j];
            split2h(v, hh[j], ll[j]);
        }
        char* da = sm + koff + ra * 80 + ds * 2;
        *(uint4*)da = *(uint4*)hh; *(uint4*)(da + 16) = *(uint4*)(hh + 8);
        *(uint4*)(da + 10240) = *(uint4*)ll; *(uint4*)(da + 10256) = *(uint4*)(ll + 8);
        const float* qs = Qb + (size_t)(k0 + rb) * LQ + cq;
#pragma unroll
        for (int j = 0; j < 4; j++) {
            float4 v = *(const float4*)(qs + j * 4);
            split2h(v.x, hh[j * 4 + 0], ll[j * 4 + 0]);
            split2h(v.y, hh[j * 4 + 1], ll[j * 4 + 1]);
            split2h(v.z, hh[j * 4 + 2], ll[j * 4 + 2]);
            split2h(v.w, hh[j * 4 + 3], ll[j * 4 + 3]);
        }
        char* db = sm + koff + 20480 + rb * 272 + cq * 2;
        *(uint4*)db = *(uint4*)hh; *(uint4*)(db + 16) = *(uint4*)(hh + 8);
        *(uint4*)(db + 8704) = *(uint4*)ll; *(uint4*)(db + 8720) = *(uint4*)(ll + 8);
    };
    stage(0);
    __syncthreads();
    build(0, 0);
    __syncthreads();
    for (int k = 0; k < 4; k++) {
        int off = (k & 1) * SBUF, noff = ((k + 1) & 1) * SBUF;
        if (k < 3) {
            stage((k + 1) * 32);      // overwrites stg: prior build reads done (last sync)
            __syncthreads();
            build(noff, (k + 1) * 32);
        }
        chunk_A2B2<272, 8, 8704>(acc, uA + off, uB + off);
        __syncthreads();
    }
    float bb = bias[0];
    int c0 = lane >> 2, nl = (lane & 3) * 2;
#pragma unroll
    for (int mf = 0; mf < 2; mf++)
#pragma unroll
        for (int rr = 0; rr < 2; rr++) {
            int gc = m0 + wm * 32 + mf * 16 + c0 + rr * 8;
            float s0 = g_sub0[b * LC + gc] + bb;
            float* row = g_S + ((size_t)(b * LC) + gc) * LQ + n0 + wn * 64;
            const float* s1 = g_sub1 + b * LQ + n0 + wn * 64;
#pragma unroll
            for (int nf = 0; nf < 8; nf++) {
                int q = nf * 8 + nl;
                row[q] = acc[mf][nf][rr * 2] + s0 + s1[q];
                row[q + 1] = acc[mf][nf][rr * 2 + 1] + s0 + s1[q + 1];
            }
        }
}

// ---------------- stats (two-pass) ----------------
__global__ __launch_bounds__(256) void k_stats(const float* __restrict__ Cmask,
                                               const float* __restrict__ Qmask) {
    __shared__ float qm[LQ];
    __shared__ float cmk[128], rmaxs[128], fr[128];
    __shared__ float sR;
    int b = blockIdx.y, c0 = blockIdx.x * 128;
    int tid = threadIdx.x, w = tid >> 5, lane = tid & 31;
    for (int i = tid; i < LQ; i += 256) qm[i] = Qmask[b * LQ + i];
    if (tid < 128) cmk[tid] = Cmask[b * LC + c0 + tid];
    __syncthreads();
    const float* Sb = g_S + ((size_t)(b * LC) + c0) * LQ;
    for (int i = 0; i < 16; i++) {
        int r = w * 16 + i;
        const float* row = Sb + (size_t)r * LQ;
        __half* Erow = g_E + ((size_t)(b * LC) + c0 + r) * LQ;
        float vals[16], m = -1e38f;
#pragma unroll
        for (int j = 0; j < 16; j++) {
            float msk = qm[lane + j * 32];
            float l = row[lane + j * 32] * msk + (1.f - msk) * NEG;
            vals[j] = l; m = fmaxf(m, l);
        }
#pragma unroll
        for (int o = 16; o; o >>= 1) m = fmaxf(m, __shfl_xor_sync(~0u, m, o));
        float sum = 0.f;
#pragma unroll
        for (int j = 0; j < 16; j++) {
            float e = __expf(vals[j] - m);
            sum += e;
            Erow[lane + j * 32] = __float2half_rn(e);
        }
#pragma unroll
        for (int o = 16; o; o >>= 1) sum += __shfl_xor_sync(~0u, sum, o);
        if (lane == 0) {
            g_rmax[b * LC + c0 + r] = m; g_rsum[b * LC + c0 + r] = sum;
            rmaxs[r] = m;
        }
    }
    __syncthreads();
    if (tid < 32) {
        float m = fmaxf(fmaxf(rmaxs[tid], rmaxs[tid + 32]),
                        fmaxf(rmaxs[tid + 64], rmaxs[tid + 96]));
#pragma unroll
        for (int o = 16; o; o >>= 1) m = fmaxf(m, __shfl_xor_sync(~0u, m, o));
        if (tid == 0) sR = m;
    }
    __syncthreads();
    if (tid < 128) fr[tid] = cmk[tid] * __expf(rmaxs[tid] - sR);
    __syncthreads();
#pragma unroll
    for (int h = 0; h < 2; h++) {
        int q = tid + h * 256;
        float z = 0.f;
        const __half* Eb = g_E + ((size_t)(b * LC) + c0) * LQ + q;
#pragma unroll 8
        for (int r = 0; r < 128; r++)
            z += fr[r] * __half2float(Eb[(size_t)r * LQ]);
        g_Zp[(b * 16 + blockIdx.x) * LQ + q] = z;
    }
    if (tid == 0) g_Rblk[b * 16 + blockIdx.x] = sR;
}
__global__ __launch_bounds__(512) void k_zrow(const float* __restrict__ Cmask) {
    __shared__ float sR;
    int b = blockIdx.x, tid = threadIdx.x;
    float R = -1e38f;
#pragma unroll
    for (int i = 0; i < 16; i++) R = fmaxf(R, g_Rblk[b * 16 + i]);
    if (tid == 0) sR = R;
    float Z = 0.f;
#pragma unroll
    for (int i = 0; i < 16; i++)
        Z += g_Zp[(b * 16 + i) * LQ + tid] * __expf(g_Rblk[b * 16 + i] - R);
    g_Z[b * LQ + tid] = Z;
    __syncthreads();
    float Rb = sR;
    for (int c = tid; c < LC; c += 512)
        g_f[b * LC + c] = Cmask[b * LC + c] * __expf(g_rmax[b * LC + c] - Rb);
}

// ---------------- GEMM T ----------------
#define TBUF 18944
#define T_ST 37888
__global__ __launch_bounds__(256) void k_T(const float* __restrict__ C) {
    extern __shared__ char sm[];
    int tid = threadIdx.x, lane = tid & 31, w = tid >> 5, wm = w & 3, wn = w >> 2;
    int b = blockIdx.y, n0 = blockIdx.x * 128;
    float* st = (float*)(sm + T_ST);
    if (tid < 128) st[tid] = 1.f / g_Z[b * LQ + n0 + tid];
    __syncthreads();
    const float* Cb = C + (size_t)b * DD * LC;
    const float* fb = g_f + b * LC;
    const __half* Eb = g_E + (size_t)b * LC * LQ + n0;
    uint32_t su = smem_u32(sm);
    uint32_t uA = su + (wm * 32 + (lane & 15)) * 80 + (lane >> 4) * 16;
    uint32_t uB = su + 10240 + (lane & 15) * 272 + (wn * 64 + (lane >> 4) * 8) * 2;
    int ar = tid >> 1, ac = (tid & 1) * 16;
    float acc[2][8][4] = {};
#pragma unroll 1
    for (int k = -1; k < 64; k++) {
        if (k + 1 < 64) {
            int noff = ((k + 1) & 1) * TBUF, kc = (k + 1) * 32;
            const float* srcC = Cb + (size_t)ar * LC + kc + ac;
            const float* fp = fb + kc + ac;
            __align__(16) __half hh[16];
#pragma unroll
            for (int j = 0; j < 4; j++) {
                float4 v = *(const float4*)(srcC + j * 4);
                float4 fv = *(const float4*)(fp + j * 4);
                hh[j * 4 + 0] = __float2half_rn(v.x * fv.x);
                hh[j * 4 + 1] = __float2half_rn(v.y * fv.y);
                hh[j * 4 + 2] = __float2half_rn(v.z * fv.z);
                hh[j * 4 + 3] = __float2half_rn(v.w * fv.w);
            }
            char* d = sm + noff + ar * 80 + ac * 2;
            *(uint4*)d = *(uint4*)hh; *(uint4*)(d + 16) = *(uint4*)(hh + 8);
            loadB128s(sm + noff + 10240, Eb + (size_t)kc * LQ, LQ, tid);
        }
        if (k >= 0) chunk_A1B1<272, 8>(acc, uA + (k & 1) * TBUF, uB + (k & 1) * TBUF);
        __syncthreads();
    }
    int c0 = lane >> 2, nl = (lane & 3) * 2;
#pragma unroll
    for (int mf = 0; mf < 2; mf++)
#pragma unroll
        for (int nf = 0; nf < 8; nf++)
#pragma unroll
            for (int rr = 0; rr < 2; rr++) {
                int d = wm * 32 + mf * 16 + c0 + rr * 8;
#pragma unroll
                for (int jj = 0; jj < 2; jj++) {
                    int ql = wn * 64 + nf * 8 + nl + jj;
                    g_T[((size_t)(b * LQ) + n0 + ql) * DD + d] =
                        acc[mf][nf][rr * 2 + jj] * st[ql];
                }
            }
}

// ---------------- GEMM F ----------------
#define FBUF 27648
#define F_ST 67584
__global__ __launch_bounds__(256) void k_F(const float* __restrict__ C,
                                           float* __restrict__ out) {
    extern __shared__ char sm[];
    int tid = threadIdx.x, lane = tid & 31, w = tid >> 5, wm = w & 3, wn = w >> 2;
    int b = blockIdx.x >> 4, m0 = (blockIdx.x & 15) * 128;
    float* st = (float*)(sm + F_ST);
    if (tid < 128) st[tid] = 1.f / g_rsum[b * LC + m0 + tid];
    __syncthreads();
    const __half* Eb = g_E + ((size_t)(b * LC) + m0) * LQ;
    const __half* BQh = g_QTh + (size_t)b * LQ * DD;
    const float* Tb = g_T + (size_t)b * LQ * DD;
    uint32_t su = smem_u32(sm);
    uint32_t uA = su + (wm * 32 + (lane & 15)) * 80 + (lane >> 4) * 16;
    uint32_t uBQ = su + 10240 + (lane & 15) * 272 + (wn * 64 + (lane >> 4) * 8) * 2;
    uint32_t uBT = su + 18944 + (lane & 15) * 272 + (wn * 64 + (lane >> 4) * 8) * 2;
    int br = tid >> 3, bc = (tid & 7) * 16;
    float accA[2][8][4] = {}, accB[2][8][4] = {};
#pragma unroll 1
    for (int k = -1; k < 16; k++) {
        if (k + 1 < 16) {
            int noff = ((k + 1) & 1) * FBUF, kq = (k + 1) * 32;
            loadA32s(sm + noff, Eb + kq, LQ, tid);
            loadB128s(sm + noff + 10240, BQh + (size_t)kq * DD, DD, tid);
            {
                const float* src = Tb + (size_t)(kq + br) * DD + bc;
                __align__(16) __half hh[16];
#pragma unroll
                for (int j = 0; j < 16; j++) hh[j] = __float2half_rn(src[j]);
                char* d = sm + noff + 18944 + br * 272 + bc * 2;
                *(uint4*)d = *(uint4*)hh; *(uint4*)(d + 16) = *(uint4*)(hh + 8);
            }
        }
        if (k >= 0) {
            int off = (k & 1) * FBUF;
            chunk_A1B1<272, 8>(accA, uA + off, uBQ + off);
            chunk_A1B1<272, 8>(accB, uA + off, uBT + off);
        }
        __syncthreads();
    }
    float* stage = (float*)sm;
    int c0 = lane >> 2, nl = (lane & 3) * 2;
#pragma unroll 1
    for (int pass = 0; pass < 2; pass++) {
        float (*acc)[8][4] = pass ? accB : accA;
#pragma unroll
        for (int mf = 0; mf < 2; mf++)
#pragma unroll
            for (int nf = 0; nf < 8; nf++)
#pragma unroll
                for (int rr = 0; rr < 2; rr++) {
                    int ml = wm * 32 + mf * 16 + c0 + rr * 8;
                    float ri = st[ml];
#pragma unroll
                    for (int jj = 0; jj < 2; jj++) {
                        int dl = wn * 64 + nf * 8 + nl + jj;
                        stage[dl * 132 + ml] = acc[mf][nf][rr * 2 + jj] * ri;
                    }
                }
        __syncthreads();
        for (int dd = 0; dd < 16; dd++) {
            int dl = w * 16 + dd;
            const float* Crow = C + ((size_t)b * DD + dl) * LC + m0;
            float* o = out + ((size_t)b * 512 + dl) * 2048 + m0;
#pragma unroll
            for (int s2 = 0; s2 < 4; s2++) {
                int cl = lane + s2 * 32;
                float cv = Crow[cl], v = stage[dl * 132 + cl];
                if (pass == 0) {
                    o[cl] = cv;
                    o[(size_t)128 * 2048 + cl] = v;
                    o[(size_t)256 * 2048 + cl] = cv * v;
                } else {
                    o[(size_t)384 * 2048 + cl] = cv * v;
                }
            }
        }
        __syncthreads();
    }
}

extern "C" void kernel_launch(void* const* d_in, const int* in_sizes, int n_in,
                              void* d_out, int out_size) {
    (void)in_sizes; (void)n_in; (void)out_size;
    const float* C     = (const float*)d_in[0];
    const float* Q     = (const float*)d_in[1];
    const float* Cmask = (const float*)d_in[2];
    const float* Qmask = (const float*)d_in[3];
    const float* w4C   = (const float*)d_in[4];
    const float* w4Q   = (const float*)d_in[5];
    const float* w4mlu = (const float*)d_in[6];
    const float* bias  = (const float*)d_in[7];
    float* out = (float*)d_out;

    const int SMEM_T = T_ST + 512;
    const int SMEM_F = F_ST + 512;
    cudaFuncSetAttribute(k_S, cudaFuncAttributeMaxDynamicSharedMemorySize, SMEM_S);
    cudaFuncSetAttribute(k_T, cudaFuncAttributeMaxDynamicSharedMemorySize, SMEM_T);
    cudaFuncSetAttribute(k_F, cudaFuncAttributeMaxDynamicSharedMemorySize, SMEM_F);

    k_zero<<<(BB * LQ + 255) / 256, 256>>>();
    k_sub0<<<dim3(LC / 256, BB), 256>>>(C, w4C);
    k_tsplit<<<dim3(LQ / 32, DD / 32, BB), dim3(32, 8)>>>(Q, w4Q);
    k_S<<<dim3(LQ / 128, LC / 128, BB), 256, SMEM_S>>>(C, Q, w4mlu, bias);
    k_stats<<<dim3(LC / 128, BB), 256>>>(Cmask, Qmask);
    k_zrow<<<BB, 512>>>(Cmask);
    k_T<<<dim3(LQ / 128, BB), 256, SMEM_T>>>(C);
    k_F<<<dim3(16 * BB), 256, SMEM_F>>>(C, out);
}

// round 17
// speedup vs baseline: 1.1326x; 1.1326x over previous
#include <cuda_runtime.h>
#include <cuda_fp16.h>
#include <cstdint>

#define BB 32
#define DD 128
#define LC 2048
#define LQ 512
#define NEG (-1e30f)

__device__ float g_S[(size_t)BB*LC*LQ];
__device__ __half g_E[(size_t)BB*LC*LQ];
__device__ float g_T[(size_t)BB*LQ*DD];
__device__ float g_sub0[BB*LC], g_sub1[BB*LQ];
__device__ float g_rmax[BB*LC], g_rsum[BB*LC];
__device__ float g_Z[BB*LQ];
__device__ float g_Zp[BB*16*LQ];
__device__ float g_Rblk[BB*16];
__device__ float g_f[BB*LC];
__device__ __half g_QTh[(size_t)BB*LQ*DD];

__device__ __forceinline__ uint32_t smem_u32(const void* p) {
    uint32_t a;
    asm("{ .reg .u64 t; cvta.to.shared.u64 t, %1; cvt.u32.u64 %0, t; }" : "=r"(a) : "l"(p));
    return a;
}
__device__ __forceinline__ void split2h(float x, __half& h, __half& l) {
    h = __float2half_rn(x);
    l = __float2half_rn(x - __half2float(h));
}
__device__ __forceinline__ void ldsm4(uint32_t* r, uint32_t a) {
    asm volatile("ldmatrix.sync.aligned.m8n8.x4.shared.b16 {%0,%1,%2,%3}, [%4];"
        : "=r"(r[0]), "=r"(r[1]), "=r"(r[2]), "=r"(r[3]) : "r"(a));
}
__device__ __forceinline__ void ldsm4t(uint32_t* r, uint32_t a) {
    asm volatile("ldmatrix.sync.aligned.m8n8.x4.trans.shared.b16 {%0,%1,%2,%3}, [%4];"
        : "=r"(r[0]), "=r"(r[1]), "=r"(r[2]), "=r"(r[3]) : "r"(a));
}
__device__ __forceinline__ void mma_f16(float* c, const uint32_t* a, const uint32_t* b) {
    asm volatile("mma.sync.aligned.m16n8k16.row.col.f32.f16.f16.f32 "
        "{%0,%1,%2,%3}, {%4,%5,%6,%7}, {%8,%9}, {%0,%1,%2,%3};"
        : "+f"(c[0]), "+f"(c[1]), "+f"(c[2]), "+f"(c[3])
        : "r"(a[0]), "r"(a[1]), "r"(a[2]), "r"(a[3]), "r"(b[0]), "r"(b[1]));
}
template<int SB, int NF, int LOFF>
__device__ __forceinline__ void chunk_A2B2(float acc[2][NF][4], uint32_t uA, uint32_t uB) {
#pragma unroll
    for (int ks = 0; ks < 2; ks++) {
        uint32_t aH[2][4], aL[2][4], bH[NF * 2], bL[NF * 2];
#pragma unroll
        for (int mf = 0; mf < 2; mf++) {
            ldsm4(aH[mf], uA + mf * 1280 + ks * 32);
            ldsm4(aL[mf], uA + 10240 + mf * 1280 + ks * 32);
        }
#pragma unroll
        for (int nb = 0; nb < NF / 2; nb++) {
            ldsm4t(&bH[nb * 4], uB + ks * 16 * SB + nb * 32);
            ldsm4t(&bL[nb * 4], uB + LOFF + ks * 16 * SB + nb * 32);
        }
#pragma unroll
        for (int mf = 0; mf < 2; mf++)
#pragma unroll
            for (int nf = 0; nf < NF; nf++) {
                mma_f16(acc[mf][nf], aH[mf], &bH[nf * 2]);
                mma_f16(acc[mf][nf], aH[mf], &bL[nf * 2]);
                mma_f16(acc[mf][nf], aL[mf], &bH[nf * 2]);
            }
    }
}
template<int SB, int NF>
__device__ __forceinline__ void chunk_A1B1(float acc[2][NF][4], uint32_t uA, uint32_t uB) {
#pragma unroll
    for (int ks = 0; ks < 2; ks++) {
        uint32_t aH[2][4], bH[NF * 2];
#pragma unroll
        for (int mf = 0; mf < 2; mf++)
            ldsm4(aH[mf], uA + mf * 1280 + ks * 32);
#pragma unroll
        for (int nb = 0; nb < NF / 2; nb++)
            ldsm4t(&bH[nb * 4], uB + ks * 16 * SB + nb * 32);
#pragma unroll
        for (int mf = 0; mf < 2; mf++)
#pragma unroll
            for (int nf = 0; nf < NF; nf++)
                mma_f16(acc[mf][nf], aH[mf], &bH[nf * 2]);
    }
}
__device__ __forceinline__ void loadA32s(char* sm, const __half* __restrict__ gh,
                                         size_t gs, int tid) {
    int r = tid >> 1, c16 = (tid & 1) * 16;
    const char* sh = (const char*)(gh + (size_t)r * gs + c16);
    char* d = sm + r * 80 + c16 * 2;
    *(uint4*)d = *(const uint4*)sh;  *(uint4*)(d + 16) = *(const uint4*)(sh + 16);
}
__device__ __forceinline__ void loadB128s(char* smB, const __half* __restrict__ gh,
                                          size_t gs, int tid) {
    int r = tid >> 3, c16 = (tid & 7) * 16;
    const char* sh = (const char*)(gh + (size_t)r * gs + c16);
    char* d = smB + r * 272 + c16 * 2;
    *(uint4*)d = *(const uint4*)sh;  *(uint4*)(d + 16) = *(const uint4*)(sh + 16);
}

// ---------------- prep ----------------
__global__ void k_zero() {
    int i = blockIdx.x * 256 + threadIdx.x;
    if (i < BB * LQ) g_sub1[i] = 0.f;
}
__global__ void k_sub0(const float* __restrict__ C, const float* __restrict__ w) {
    int b = blockIdx.y, c = blockIdx.x * 256 + threadIdx.x;
    const float* Cb = C + (size_t)b * DD * LC;
    float acc = 0.f;
#pragma unroll 8
    for (int d = 0; d < DD; d++) acc += Cb[(size_t)d * LC + c] * w[d];
    g_sub0[b * LC + c] = acc;
}
__global__ void k_tsplit(const float* __restrict__ src, const float* __restrict__ wsub) {
    __shared__ float t[32][33];
    __shared__ float ps[32];
    int b = blockIdx.z, x0 = blockIdx.x * 32, d0 = blockIdx.y * 32;
    int tx = threadIdx.x, ty = threadIdx.y;
    if (ty == 0) ps[tx] = 0.f;
    __syncthreads();
    const float* s = src + ((size_t)b * DD + d0) * LQ + x0;
    float psum = 0.f;
#pragma unroll
    for (int i = 0; i < 4; i++) {
        int d = ty + i * 8;
        float v = s[(size_t)d * LQ + tx];
        psum += v * wsub[d0 + d];
        t[d][tx] = v;
    }
    atomicAdd(&ps[tx], psum);
    __syncthreads();
#pragma unroll
    for (int i = 0; i < 4; i++) {
        int x = ty + i * 8;
        size_t o = ((size_t)b * LQ + x0 + x) * DD + d0 + tx;
        g_QTh[o] = __float2half_rn(t[tx][x]);
    }
    if (ty == 0) atomicAdd(g_sub1 + b * LQ + x0 + tx, ps[tx]);
}

// ---------------- GEMM S: on-the-fly tiles, coalesced A gather ----------------
#define SBUF 37888
#define S_WML 75776
#define SMEM_S 76288
__global__ __launch_bounds__(256) void k_S(const float* __restrict__ C,
                                           const float* __restrict__ Q,
                                           const float* __restrict__ w4mlu,
                                           const float* __restrict__ bias) {
    extern __shared__ char sm[];
    float* wml = (float*)(sm + S_WML);
    int tid = threadIdx.x, lane = tid & 31, w = tid >> 5, wm = w & 3, wn = w >> 2;
    int b = blockIdx.z, m0 = blockIdx.y * 128, n0 = blockIdx.x * 128;
    if (tid < 128) wml[tid] = w4mlu[tid];
    __syncthreads();
    const float* Cb = C + (size_t)b * DD * LC + m0;
    const float* Qb = Q + (size_t)b * DD * LQ + n0;
    uint32_t su = smem_u32(sm);
    uint32_t uA = su + (wm * 32 + (lane & 15)) * 80 + (lane >> 4) * 16;
    uint32_t uB = su + 20480 + (lane & 15) * 272 + (wn * 64 + (lane >> 4) * 8) * 2;
    // A-build mapping: warp covers 32 consecutive c at same d -> coalesced 128B lines
    int ra = ((w & 3) << 5) + lane, ds = (w >> 2) * 16;
    int rb = tid >> 3, cq = (tid & 7) * 16;
    float acc[2][8][4] = {};
    auto build = [&](int koff, int k0) {
        __align__(16) __half hh[16], ll[16];
#pragma unroll
        for (int j = 0; j < 16; j++) {
            int d = k0 + ds + j;
            float v = Cb[(size_t)d * LC + ra] * wml[d];
            split2h(v, hh[j], ll[j]);
        }
        char* da = sm + koff + ra * 80 + ds * 2;
        *(uint4*)da = *(uint4*)hh; *(uint4*)(da + 16) = *(uint4*)(hh + 8);
        *(uint4*)(da + 10240) = *(uint4*)ll; *(uint4*)(da + 10256) = *(uint4*)(ll + 8);
        const float* qs = Qb + (size_t)(k0 + rb) * LQ + cq;
#pragma unroll
        for (int j = 0; j < 4; j++) {
            float4 v = *(const float4*)(qs + j * 4);
            split2h(v.x, hh[j * 4 + 0], ll[j * 4 + 0]);
            split2h(v.y, hh[j * 4 + 1], ll[j * 4 + 1]);
            split2h(v.z, hh[j * 4 + 2], ll[j * 4 + 2]);
            split2h(v.w, hh[j * 4 + 3], ll[j * 4 + 3]);
        }
        char* db = sm + koff + 20480 + rb * 272 + cq * 2;
        *(uint4*)db = *(uint4*)hh; *(uint4*)(db + 16) = *(uint4*)(hh + 8);
        *(uint4*)(db + 8704) = *(uint4*)ll; *(uint4*)(db + 8720) = *(uint4*)(ll + 8);
    };
    build(0, 0);
    __syncthreads();
    for (int k = 0; k < 4; k++) {
        int off = (k & 1) * SBUF, noff = ((k + 1) & 1) * SBUF;
        if (k < 3) build(noff, (k + 1) * 32);
        chunk_A2B2<272, 8, 8704>(acc, uA + off, uB + off);
        __syncthreads();
    }
    float bb = bias[0];
    int c0 = lane >> 2, nl = (lane & 3) * 2;
#pragma unroll
    for (int mf = 0; mf < 2; mf++)
#pragma unroll
        for (int rr = 0; rr < 2; rr++) {
            int gc = m0 + wm * 32 + mf * 16 + c0 + rr * 8;
            float s0 = g_sub0[b * LC + gc] + bb;
            float* row = g_S + ((size_t)(b * LC) + gc) * LQ + n0 + wn * 64;
            const float* s1 = g_sub1 + b * LQ + n0 + wn * 64;
#pragma unroll
            for (int nf = 0; nf < 8; nf++) {
                int q = nf * 8 + nl;
                row[q] = acc[mf][nf][rr * 2] + s0 + s1[q];
                row[q + 1] = acc[mf][nf][rr * 2 + 1] + s0 + s1[q + 1];
            }
        }
}

// ---------------- stats (two-pass) ----------------
__global__ __launch_bounds__(256) void k_stats(const float* __restrict__ Cmask,
                                               const float* __restrict__ Qmask) {
    __shared__ float qm[LQ];
    __shared__ float cmk[128], rmaxs[128], fr[128];
    __shared__ float sR;
    int b = blockIdx.y, c0 = blockIdx.x * 128;
    int tid = threadIdx.x, w = tid >> 5, lane = tid & 31;
    for (int i = tid; i < LQ; i += 256) qm[i] = Qmask[b * LQ + i];
    if (tid < 128) cmk[tid] = Cmask[b * LC + c0 + tid];
    __syncthreads();
    const float* Sb = g_S + ((size_t)(b * LC) + c0) * LQ;
    for (int i = 0; i < 16; i++) {
        int r = w * 16 + i;
        const float* row = Sb + (size_t)r * LQ;
        __half* Erow = g_E + ((size_t)(b * LC) + c0 + r) * LQ;
        float vals[16], m = -1e38f;
#pragma unroll
        for (int j = 0; j < 16; j++) {
            float msk = qm[lane + j * 32];
            float l = row[lane + j * 32] * msk + (1.f - msk) * NEG;
            vals[j] = l; m = fmaxf(m, l);
        }
#pragma unroll
        for (int o = 16; o; o >>= 1) m = fmaxf(m, __shfl_xor_sync(~0u, m, o));
        float sum = 0.f;
#pragma unroll
        for (int j = 0; j < 16; j++) {
            float e = __expf(vals[j] - m);
            sum += e;
            Erow[lane + j * 32] = __float2half_rn(e);
        }
#pragma unroll
        for (int o = 16; o; o >>= 1) sum += __shfl_xor_sync(~0u, sum, o);
        if (lane == 0) {
            g_rmax[b * LC + c0 + r] = m; g_rsum[b * LC + c0 + r] = sum;
            rmaxs[r] = m;
        }
    }
    __syncthreads();
    if (tid < 32) {
        float m = fmaxf(fmaxf(rmaxs[tid], rmaxs[tid + 32]),
                        fmaxf(rmaxs[tid + 64], rmaxs[tid + 96]));
#pragma unroll
        for (int o = 16; o; o >>= 1) m = fmaxf(m, __shfl_xor_sync(~0u, m, o));
        if (tid == 0) sR = m;
    }
    __syncthreads();
    if (tid < 128) fr[tid] = cmk[tid] * __expf(rmaxs[tid] - sR);
    __syncthreads();
#pragma unroll
    for (int h = 0; h < 2; h++) {
        int q = tid + h * 256;
        float z = 0.f;
        const __half* Eb = g_E + ((size_t)(b * LC) + c0) * LQ + q;
#pragma unroll 8
        for (int r = 0; r < 128; r++)
            z += fr[r] * __half2float(Eb[(size_t)r * LQ]);
        g_Zp[(b * 16 + blockIdx.x) * LQ + q] = z;
    }
    if (tid == 0) g_Rblk[b * 16 + blockIdx.x] = sR;
}
__global__ __launch_bounds__(512) void k_zrow(const float* __restrict__ Cmask) {
    __shared__ float sR;
    int b = blockIdx.x, tid = threadIdx.x;
    float R = -1e38f;
#pragma unroll
    for (int i = 0; i < 16; i++) R = fmaxf(R, g_Rblk[b * 16 + i]);
    if (tid == 0) sR = R;
    float Z = 0.f;
#pragma unroll
    for (int i = 0; i < 16; i++)
        Z += g_Zp[(b * 16 + i) * LQ + tid] * __expf(g_Rblk[b * 16 + i] - R);
    g_Z[b * LQ + tid] = Z;
    __syncthreads();
    float Rb = sR;
    for (int c = tid; c < LC; c += 512)
        g_f[b * LC + c] = Cmask[b * LC + c] * __expf(g_rmax[b * LC + c] - Rb);
}

// ---------------- GEMM T ----------------
#define TBUF 18944
#define T_ST 37888
__global__ __launch_bounds__(256) void k_T(const float* __restrict__ C) {
    extern __shared__ char sm[];
    int tid = threadIdx.x, lane = tid & 31, w = tid >> 5, wm = w & 3, wn = w >> 2;
    int b = blockIdx.y, n0 = blockIdx.x * 128;
    float* st = (float*)(sm + T_ST);
    if (tid < 128) st[tid] = 1.f / g_Z[b * LQ + n0 + tid];
    __syncthreads();
    const float* Cb = C + (size_t)b * DD * LC;
    const float* fb = g_f + b * LC;
    const __half* Eb = g_E + (size_t)b * LC * LQ + n0;
    uint32_t su = smem_u32(sm);
    uint32_t uA = su + (wm * 32 + (lane & 15)) * 80 + (lane >> 4) * 16;
    uint32_t uB = su + 10240 + (lane & 15) * 272 + (wn * 64 + (lane >> 4) * 8) * 2;
    int ar = tid >> 1, ac = (tid & 1) * 16;
    float acc[2][8][4] = {};
#pragma unroll 1
    for (int k = -1; k < 64; k++) {
        if (k + 1 < 64) {
            int noff = ((k + 1) & 1) * TBUF, kc = (k + 1) * 32;
            const float* srcC = Cb + (size_t)ar * LC + kc + ac;
            const float* fp = fb + kc + ac;
            __align__(16) __half hh[16];
#pragma unroll
            for (int j = 0; j < 4; j++) {
                float4 v = *(const float4*)(srcC + j * 4);
                float4 fv = *(const float4*)(fp + j * 4);
                hh[j * 4 + 0] = __float2half_rn(v.x * fv.x);
                hh[j * 4 + 1] = __float2half_rn(v.y * fv.y);
                hh[j * 4 + 2] = __float2half_rn(v.z * fv.z);
                hh[j * 4 + 3] = __float2half_rn(v.w * fv.w);
            }
            char* d = sm + noff + ar * 80 + ac * 2;
            *(uint4*)d = *(uint4*)hh; *(uint4*)(d + 16) = *(uint4*)(hh + 8);
            loadB128s(sm + noff + 10240, Eb + (size_t)kc * LQ, LQ, tid);
        }
        if (k >= 0) chunk_A1B1<272, 8>(acc, uA + (k & 1) * TBUF, uB + (k & 1) * TBUF);
        __syncthreads();
    }
    int c0 = lane >> 2, nl = (lane & 3) * 2;
#pragma unroll
    for (int mf = 0; mf < 2; mf++)
#pragma unroll
        for (int nf = 0; nf < 8; nf++)
#pragma unroll
            for (int rr = 0; rr < 2; rr++) {
                int d = wm * 32 + mf * 16 + c0 + rr * 8;
#pragma unroll
                for (int jj = 0; jj < 2; jj++) {
                    int ql = wn * 64 + nf * 8 + nl + jj;
                    g_T[((size_t)(b * LQ) + n0 + ql) * DD + d] =
                        acc[mf][nf][rr * 2 + jj] * st[ql];
                }
            }
}

// ---------------- GEMM F ----------------
#define FBUF 27648
#define F_ST 67584
__global__ __launch_bounds__(256) void k_F(const float* __restrict__ C,
                                           float* __restrict__ out) {
    extern __shared__ char sm[];
    int tid = threadIdx.x, lane = tid & 31, w = tid >> 5, wm = w & 3, wn = w >> 2;
    int b = blockIdx.x >> 4, m0 = (blockIdx.x & 15) * 128;
    float* st = (float*)(sm + F_ST);
    if (tid < 128) st[tid] = 1.f / g_rsum[b * LC + m0 + tid];
    __syncthreads();
    const __half* Eb = g_E + ((size_t)(b * LC) + m0) * LQ;
    const __half* BQh = g_QTh + (size_t)b * LQ * DD;
    const float* Tb = g_T + (size_t)b * LQ * DD;
    uint32_t su = smem_u32(sm);
    uint32_t uA = su + (wm * 32 + (lane & 15)) * 80 + (lane >> 4) * 16;
    uint32_t uBQ = su + 10240 + (lane & 15) * 272 + (wn * 64 + (lane >> 4) * 8) * 2;
    uint32_t uBT = su + 18944 + (lane & 15) * 272 + (wn * 64 + (lane >> 4) * 8) * 2;
    int br = tid >> 3, bc = (tid & 7) * 16;
    float accA[2][8][4] = {}, accB[2][8][4] = {};
#pragma unroll 1
    for (int k = -1; k < 16; k++) {
        if (k + 1 < 16) {
            int noff = ((k + 1) & 1) * FBUF, kq = (k + 1) * 32;
            loadA32s(sm + noff, Eb + kq, LQ, tid);
            loadB128s(sm + noff + 10240, BQh + (size_t)kq * DD, DD, tid);
            {
                const float* src = Tb + (size_t)(kq + br) * DD + bc;
                __align__(16) __half hh[16];
#pragma unroll
                for (int j = 0; j < 16; j++) hh[j] = __float2half_rn(src[j]);
                char* d = sm + noff + 18944 + br * 272 + bc * 2;
                *(uint4*)d = *(uint4*)hh; *(uint4*)(d + 16) = *(uint4*)(hh + 8);
            }
        }
        if (k >= 0) {
            int off = (k & 1) * FBUF;
            chunk_A1B1<272, 8>(accA, uA + off, uBQ + off);
            chunk_A1B1<272, 8>(accB, uA + off, uBT + off);
        }
        __syncthreads();
    }
    float* stage = (float*)sm;
    int c0 = lane >> 2, nl = (lane & 3) * 2;
#pragma unroll 1
    for (int pass = 0; pass < 2; pass++) {
        float (*acc)[8][4] = pass ? accB : accA;
#pragma unroll
        for (int mf = 0; mf < 2; mf++)
#pragma unroll
            for (int nf = 0; nf < 8; nf++)
#pragma unroll
                for (int rr = 0; rr < 2; rr++) {
                    int ml = wm * 32 + mf * 16 + c0 + rr * 8;
                    float ri = st[ml];
#pragma unroll
                    for (int jj = 0; jj < 2; jj++) {
                        int dl = wn * 64 + nf * 8 + nl + jj;
                        stage[dl * 132 + ml] = acc[mf][nf][rr * 2 + jj] * ri;
                    }
                }
        __syncthreads();
        for (int dd = 0; dd < 16; dd++) {
            int dl = w * 16 + dd;
            const float* Crow = C + ((size_t)b * DD + dl) * LC + m0;
            float* o = out + ((size_t)b * 512 + dl) * 2048 + m0;
#pragma unroll
            for (int s2 = 0; s2 < 4; s2++) {
                int cl = lane + s2 * 32;
                float cv = Crow[cl], v = stage[dl * 132 + cl];
                if (pass == 0) {
                    o[cl] = cv;
                    o[(size_t)128 * 2048 + cl] = v;
                    o[(size_t)256 * 2048 + cl] = cv * v;
                } else {
                    o[(size_t)384 * 2048 + cl] = cv * v;
                }
            }
        }
        __syncthreads();
    }
}

extern "C" void kernel_launch(void* const* d_in, const int* in_sizes, int n_in,
                              void* d_out, int out_size) {
    (void)in_sizes; (void)n_in; (void)out_size;
    const float* C     = (const float*)d_in[0];
    const float* Q     = (const float*)d_in[1];
    const float* Cmask = (const float*)d_in[2];
    const float* Qmask = (const float*)d_in[3];
    const float* w4C   = (const float*)d_in[4];
    const float* w4Q   = (const float*)d_in[5];
    const float* w4mlu = (const float*)d_in[6];
    const float* bias  = (const float*)d_in[7];
    float* out = (float*)d_out;

    const int SMEM_T = T_ST + 512;
    const int SMEM_F = F_ST + 512;
    cudaFuncSetAttribute(k_S, cudaFuncAttributeMaxDynamicSharedMemorySize, SMEM_S);
    cudaFuncSetAttribute(k_T, cudaFuncAttributeMaxDynamicSharedMemorySize, SMEM_T);
    cudaFuncSetAttribute(k_F, cudaFuncAttributeMaxDynamicSharedMemorySize, SMEM_F);

    k_zero<<<(BB * LQ + 255) / 256, 256>>>();
    k_sub0<<<dim3(LC / 256, BB), 256>>>(C, w4C);
    k_tsplit<<<dim3(LQ / 32, DD / 32, BB), dim3(32, 8)>>>(Q, w4Q);
    k_S<<<dim3(LQ / 128, LC / 128, BB), 256, SMEM_S>>>(C, Q, w4mlu, bias);
    k_stats<<<dim3(LC / 128, BB), 256>>>(Cmask, Qmask);
    k_zrow<<<BB, 512>>>(Cmask);
    k_T<<<dim3(LQ / 128, BB), 256, SMEM_T>>>(C);
    k_F<<<dim3(16 * BB), 256, SMEM_F>>>(C, out);
}